// round 7
// baseline (speedup 1.0000x reference)
#include <cuda_runtime.h>

// Problem constants (fixed by the dataset)
#define BB    16
#define NCAM  6
#define PP    70000
#define HH    112
#define WW    200
#define BSN   (BB * NCAM)      // 96
#define HW    (HH * WW)        // 22400
#define BEV   200              // bev_side

// ---------------- device scratch (static: no allocation allowed) -----------
// Interleaved keyed winner grid: per cell, .x = depth entry, .y = ilu entry.
// Each entry: high 32 bits = (point index + 1), low 32 bits = payload float
// bits. Point index is unique per camera, so 64-bit max ordering is decided
// entirely by the high word -> winning entry carries the winner's payload
// bit-exactly, replicating JAX last-write-wins scatter (max-p point wins).
__device__ ulonglong2 g_k[BSN * HW];    // 34.4 MB
__device__ float g_M[BSN][12];          // per camera: (K4 @ Einv) @ inv(view)

// ---------------- 4x4 inverse (adjugate, row-major) -------------------------
__device__ void inv4x4(const float* m, float* inv) {
    float a00=m[0], a01=m[1], a02=m[2], a03=m[3];
    float a10=m[4], a11=m[5], a12=m[6], a13=m[7];
    float a20=m[8], a21=m[9], a22=m[10],a23=m[11];
    float a30=m[12],a31=m[13],a32=m[14],a33=m[15];
    float b00=a00*a11-a01*a10, b01=a00*a12-a02*a10, b02=a00*a13-a03*a10;
    float b03=a01*a12-a02*a11, b04=a01*a13-a03*a11, b05=a02*a13-a03*a12;
    float b06=a20*a31-a21*a30, b07=a20*a32-a22*a30, b08=a20*a33-a23*a30;
    float b09=a21*a32-a22*a31, b10=a21*a33-a23*a31, b11=a22*a33-a23*a32;
    float det = b00*b11 - b01*b10 + b02*b09 + b03*b08 - b04*b07 + b05*b06;
    float id = 1.0f / det;
    inv[0]  = ( a11*b11 - a12*b10 + a13*b09)*id;
    inv[1]  = (-a01*b11 + a02*b10 - a03*b09)*id;
    inv[2]  = ( a31*b05 - a32*b04 + a33*b03)*id;
    inv[3]  = (-a21*b05 + a22*b04 - a23*b03)*id;
    inv[4]  = (-a10*b11 + a12*b08 - a13*b07)*id;
    inv[5]  = ( a00*b11 - a02*b08 + a03*b07)*id;
    inv[6]  = (-a30*b05 + a32*b02 - a33*b01)*id;
    inv[7]  = ( a20*b05 - a22*b02 + a23*b01)*id;
    inv[8]  = ( a10*b10 - a11*b08 + a13*b06)*id;
    inv[9]  = (-a00*b10 + a01*b08 - a03*b06)*id;
    inv[10] = ( a30*b04 - a31*b02 + a33*b00)*id;
    inv[11] = (-a20*b04 + a21*b02 - a23*b00)*id;
    inv[12] = (-a10*b09 + a11*b07 - a12*b06)*id;
    inv[13] = ( a00*b09 - a01*b07 + a02*b06)*id;
    inv[14] = (-a30*b03 + a31*b01 - a32*b00)*id;
    inv[15] = ( a20*b03 - a21*b01 + a22*b00)*id;
}

// ---------------- kernel 0: zero keyed grid + matrix precompute -------------
// 16B vectorized zeroing; block 0 also computes the fused per-camera matrices
// M = (K4 @ Einv) @ inv(view)  (tiny, runs alongside the memset).
__global__ void __launch_bounds__(256)
k_setup(const float* __restrict__ E4,   // (B,S,N,4,4)
        const float* __restrict__ K3,   // (B,S,N,3,3)
        const float* __restrict__ V4)   // (B,1,1,4,4)
{
    int i = blockIdx.x * blockDim.x + threadIdx.x;
    // BSN*HW = 2,150,400 cells -> /256 = 8400 blocks exact, one 16B store each
    g_k[i] = make_ulonglong2(0ull, 0ull);

    if (blockIdx.x == 0) {
        __shared__ float sInvV[BB][16];
        int t = threadIdx.x;
        if (t >= 96 && t < 96 + BB) {
            inv4x4(V4 + (t - 96) * 16, sInvV[t - 96]);
        }
        __syncthreads();
        if (t < BSN) {
            const float* e = E4 + t * 16;
            const float* k = K3 + t * 9;
            // Einv (top 3 rows): rotation R^T, translation -R^T t
            float Ei[3][4];
            #pragma unroll
            for (int r = 0; r < 3; r++) {
                float r0 = e[0*4 + r], r1 = e[1*4 + r], r2 = e[2*4 + r];
                Ei[r][0] = r0; Ei[r][1] = r1; Ei[r][2] = r2;
                Ei[r][3] = -(r0 * e[3] + r1 * e[7] + r2 * e[11]);
            }
            const float sx = 0.25f, sy = 0.25f;
            float f0 = k[0] * sx, c0 = k[2] * sx;
            float f1 = k[4] * sy, c1 = k[5] * sy;
            // A = K4 @ Einv (rows 0..2); A row3 would be (0,0,0,1)
            float A[3][4];
            #pragma unroll
            for (int j = 0; j < 4; j++) {
                A[0][j] = f0 * Ei[0][j] + c0 * Ei[2][j];
                A[1][j] = f1 * Ei[1][j] + c1 * Ei[2][j];
                A[2][j] = Ei[2][j];
            }
            // M = A @ inv(view); inv(view) row 3 == (0,0,0,1)
            const float* iv = sInvV[t / NCAM];
            float* M = g_M[t];
            #pragma unroll
            for (int r = 0; r < 3; r++) {
                #pragma unroll
                for (int j = 0; j < 4; j++) {
                    float s = A[r][0]*iv[0*4 + j] + A[r][1]*iv[1*4 + j]
                            + A[r][2]*iv[2*4 + j];
                    if (j == 3) s += A[r][3];
                    M[r*4 + j] = s;
                }
            }
        }
    }
}

// ---------------- kernel 1: per-point projection + keyed winner scatter ----
__global__ void __launch_bounds__(256)
k_points(const float* __restrict__ pcloud)   // (B,1,1,P,4)
{
    int idx = blockIdx.x * blockDim.x + threadIdx.x;   // exact grid, all warps full
    int b = idx / PP;
    int p = idx - b * PP;

    float4 pt = reinterpret_cast<const float4*>(pcloud)[idx];
    float ilu = pt.w;
    int lane = threadIdx.x & 31;
    unsigned long long key = ((unsigned long long)(p + 1)) << 32;

    #pragma unroll
    for (int n = 0; n < NCAM; n++) {
        int bn = b * NCAM + n;
        const float* M = g_M[bn];
        float px = M[0]*pt.x + M[1]*pt.y + M[2] *pt.z + M[3];
        float py = M[4]*pt.x + M[5]*pt.y + M[6] *pt.z + M[7];
        float z  = M[8]*pt.x + M[9]*pt.y + M[10]*pt.z + M[11];

        float denom = fmaxf(z, 1e-6f);
        float x_ = px / denom;
        float y_ = py / denom;

        bool v = (x_ > -0.5f) & (x_ < (float)WW - 0.5f) &
                 (y_ > -0.5f) & (y_ < (float)HH - 0.5f) & (z > 0.0f);
        float valid = v ? 1.0f : 0.0f;
        float depth = fminf(fmaxf(z, 0.0f), (float)(BEV/2 - 1)) * valid;
        float vilu  = fminf(fmaxf(ilu * valid, 0.0f), 255.0f);

        int ym = (int)fminf(fmaxf(y_, 0.0f), (float)(HH - 1));
        int xm = (int)fminf(fmaxf(x_, 0.0f), (float)(WW - 1));
        int cell = bn * HW + ym * WW + xm;

        // Warp-aggregated keyed max-scatter: p is monotonic with lane within a
        // warp (and lanes with different b can never share a cell since bn
        // differs), so the highest lane of each same-cell peer group holds the
        // group-max p and its own (correct) payload. Two fire-and-forget REDs
        // per distinct cell per warp, to adjacent addresses (same 128B line).
        unsigned peers  = __match_any_sync(0xffffffffu, cell);
        int      leader = 31 - __clz(peers);
        if (lane == leader) {
            atomicMax(&g_k[cell].x, key | (unsigned long long)__float_as_uint(depth));
            atomicMax(&g_k[cell].y, key | (unsigned long long)__float_as_uint(vilu));
        }
    }
}

// ---------------- kernel 2: coalesced grid read + output write -------------
// One cell per thread: 16B vector load, scalar stores to both planes.
// No dependent gather anywhere.
__global__ void __launch_bounds__(256)
k_cells(float* __restrict__ out)   // (bsn, 2, H, W)
{
    int c = blockIdx.x * blockDim.x + threadIdx.x;   // cell within plane
    if (c >= HW) return;
    int bn = blockIdx.y;

    ulonglong2 k = g_k[bn * HW + c];

    float d  = (k.x >> 32) ? __uint_as_float((unsigned)k.x) * 0.01f : 0.0f;
    float il = (k.y >> 32) ? log1pf(__uint_as_float((unsigned)k.y)) * 0.18033688011112042f
                           : 0.0f;

    out[(bn * 2    ) * HW + c] = d;
    out[(bn * 2 + 1) * HW + c] = il;
}

// ---------------- launch ----------------------------------------------------
extern "C" void kernel_launch(void* const* d_in, const int* in_sizes, int n_in,
                              void* d_out, int out_size)
{
    const float* pc = (const float*)d_in[0];  // pcloud
    const float* E  = (const float*)d_in[1];  // extrinsics
    const float* K  = (const float*)d_in[2];  // intrinsics
    const float* V  = (const float*)d_in[3];  // view
    float* out = (float*)d_out;

    k_setup<<<(BSN * HW) / 256, 256>>>(E, K, V);   // 8400 blocks exact
    k_points<<<(BB * PP) / 256, 256>>>(pc);        // 4375 blocks exact
    dim3 cgrid((HW + 255) / 256, BSN);
    k_cells<<<cgrid, 256>>>(out);
}

// round 14
// speedup vs baseline: 1.7240x; 1.7240x over previous
#include <cuda_runtime.h>

// Problem constants (fixed by the dataset)
#define BB    16
#define NCAM  6
#define PP    70000
#define HH    112
#define WW    200
#define BSN   (BB * NCAM)      // 96
#define HW    (HH * WW)        // 22400
#define BEV   200              // bev_side

// ---------------- device scratch (static: no allocation allowed) -----------
// Winner grid: per cell, (point index + 1) of the max-p point that scattered
// there (0 = untouched). Max-p == last-write-wins in JAX scatter order.
// Payloads are NOT stored; k_cells re-projects the single winner point.
__device__ int   g_w[BSN * HW];         // 8.6 MB
__device__ float g_M[BSN][12];          // per camera: (K4 @ Einv) @ inv(view)

// ---------------- 4x4 inverse (adjugate, row-major) -------------------------
__device__ void inv4x4(const float* m, float* inv) {
    float a00=m[0], a01=m[1], a02=m[2], a03=m[3];
    float a10=m[4], a11=m[5], a12=m[6], a13=m[7];
    float a20=m[8], a21=m[9], a22=m[10],a23=m[11];
    float a30=m[12],a31=m[13],a32=m[14],a33=m[15];
    float b00=a00*a11-a01*a10, b01=a00*a12-a02*a10, b02=a00*a13-a03*a10;
    float b03=a01*a12-a02*a11, b04=a01*a13-a03*a11, b05=a02*a13-a03*a12;
    float b06=a20*a31-a21*a30, b07=a20*a32-a22*a30, b08=a20*a33-a23*a30;
    float b09=a21*a32-a22*a31, b10=a21*a33-a23*a31, b11=a22*a33-a23*a32;
    float det = b00*b11 - b01*b10 + b02*b09 + b03*b08 - b04*b07 + b05*b06;
    float id = 1.0f / det;
    inv[0]  = ( a11*b11 - a12*b10 + a13*b09)*id;
    inv[1]  = (-a01*b11 + a02*b10 - a03*b09)*id;
    inv[2]  = ( a31*b05 - a32*b04 + a33*b03)*id;
    inv[3]  = (-a21*b05 + a22*b04 - a23*b03)*id;
    inv[4]  = (-a10*b11 + a12*b08 - a13*b07)*id;
    inv[5]  = ( a00*b11 - a02*b08 + a03*b07)*id;
    inv[6]  = (-a30*b05 + a32*b02 - a33*b01)*id;
    inv[7]  = ( a20*b05 - a22*b02 + a23*b01)*id;
    inv[8]  = ( a10*b10 - a11*b08 + a13*b06)*id;
    inv[9]  = (-a00*b10 + a01*b08 - a03*b06)*id;
    inv[10] = ( a30*b04 - a31*b02 + a33*b00)*id;
    inv[11] = (-a20*b04 + a21*b02 - a23*b00)*id;
    inv[12] = (-a10*b09 + a11*b07 - a12*b06)*id;
    inv[13] = ( a00*b09 - a01*b07 + a02*b06)*id;
    inv[14] = (-a30*b03 + a31*b01 - a32*b00)*id;
    inv[15] = ( a20*b03 - a21*b01 + a22*b00)*id;
}

// ---------------- kernel 0: zero winner grid + matrix precompute ------------
// int4 vectorized zeroing (8.6 MB); block 0 also computes the fused
// per-camera matrices M = (K4 @ Einv) @ inv(view).
__global__ void __launch_bounds__(256)
k_setup(const float* __restrict__ E4,   // (B,S,N,4,4)
        const float* __restrict__ K3,   // (B,S,N,3,3)
        const float* __restrict__ V4)   // (B,1,1,4,4)
{
    int i = blockIdx.x * blockDim.x + threadIdx.x;
    // BSN*HW = 2,150,400 ints -> 537,600 int4 -> /256 = 2100 blocks exact
    reinterpret_cast<int4*>(g_w)[i] = make_int4(0, 0, 0, 0);

    if (blockIdx.x == 0) {
        __shared__ float sInvV[BB][16];
        int t = threadIdx.x;
        if (t >= 96 && t < 96 + BB) {
            inv4x4(V4 + (t - 96) * 16, sInvV[t - 96]);
        }
        __syncthreads();
        if (t < BSN) {
            const float* e = E4 + t * 16;
            const float* k = K3 + t * 9;
            // Einv (top 3 rows): rotation R^T, translation -R^T t
            float Ei[3][4];
            #pragma unroll
            for (int r = 0; r < 3; r++) {
                float r0 = e[0*4 + r], r1 = e[1*4 + r], r2 = e[2*4 + r];
                Ei[r][0] = r0; Ei[r][1] = r1; Ei[r][2] = r2;
                Ei[r][3] = -(r0 * e[3] + r1 * e[7] + r2 * e[11]);
            }
            const float sx = 0.25f, sy = 0.25f;
            float f0 = k[0] * sx, c0 = k[2] * sx;
            float f1 = k[4] * sy, c1 = k[5] * sy;
            // A = K4 @ Einv (rows 0..2)
            float A[3][4];
            #pragma unroll
            for (int j = 0; j < 4; j++) {
                A[0][j] = f0 * Ei[0][j] + c0 * Ei[2][j];
                A[1][j] = f1 * Ei[1][j] + c1 * Ei[2][j];
                A[2][j] = Ei[2][j];
            }
            // M = A @ inv(view); inv(view) row 3 == (0,0,0,1)
            const float* iv = sInvV[t / NCAM];
            float* M = g_M[t];
            #pragma unroll
            for (int r = 0; r < 3; r++) {
                #pragma unroll
                for (int j = 0; j < 4; j++) {
                    float s = A[r][0]*iv[0*4 + j] + A[r][1]*iv[1*4 + j]
                            + A[r][2]*iv[2*4 + j];
                    if (j == 3) s += A[r][3];
                    M[r*4 + j] = s;
                }
            }
        }
    }
}

// ---------------- kernel 1: per-point projection + winner scatter ----------
// Only the cell index is computed here (no payload math, no payload stores).
// One warp-aggregated 32-bit RED.MAX per distinct cell per warp per camera.
__global__ void __launch_bounds__(256)
k_points(const float* __restrict__ pcloud)   // (B,1,1,P,4)
{
    int idx = blockIdx.x * blockDim.x + threadIdx.x;   // exact grid, all warps full
    int b = idx / PP;
    int p = idx - b * PP;

    float4 pt = reinterpret_cast<const float4*>(pcloud)[idx];
    int lane = threadIdx.x & 31;

    #pragma unroll
    for (int n = 0; n < NCAM; n++) {
        int bn = b * NCAM + n;
        const float* M = g_M[bn];
        float px = M[0]*pt.x + M[1]*pt.y + M[2] *pt.z + M[3];
        float py = M[4]*pt.x + M[5]*pt.y + M[6] *pt.z + M[7];
        float z  = M[8]*pt.x + M[9]*pt.y + M[10]*pt.z + M[11];

        float denom = fmaxf(z, 1e-6f);
        float x_ = px / denom;
        float y_ = py / denom;

        int ym = (int)fminf(fmaxf(y_, 0.0f), (float)(HH - 1));
        int xm = (int)fminf(fmaxf(x_, 0.0f), (float)(WW - 1));
        int cell = bn * HW + ym * WW + xm;

        // Warp-aggregated max-scatter: p is monotonic with lane within a warp
        // (lanes with different b can never share a cell since bn differs), so
        // the highest lane of each same-cell peer group carries the group max.
        unsigned peers  = __match_any_sync(0xffffffffu, cell);
        int      leader = 31 - __clz(peers);
        if (lane == leader) atomicMax(&g_w[cell], p + 1);
    }
}

// ---------------- kernel 2: winner re-projection + output write ------------
// Four cells per thread: one int4 winner load, up to 4 INDEPENDENT pcloud
// gathers issued back-to-back (MLP=4 hides L2 latency), then float4 stores
// to both planes. pcloud (17.9 MB) is L2-warm after k_points.
__global__ void __launch_bounds__(256)
k_cells(const float* __restrict__ pcloud, float* __restrict__ out)
{
    int q = blockIdx.x * blockDim.x + threadIdx.x;   // quad index within plane
    if (q >= HW / 4) return;                          // HW/4 = 5600
    int bn = blockIdx.y;
    int b  = bn / NCAM;
    const float* M = g_M[bn];

    int4 w4 = reinterpret_cast<const int4*>(g_w)[bn * (HW / 4) + q];
    int w[4] = {w4.x, w4.y, w4.z, w4.w};

    // Issue all gathers before any dependent use (independent loads, MLP=4)
    float4 pt[4];
    #pragma unroll
    for (int j = 0; j < 4; j++) {
        int src = (w[j] > 0) ? (b * PP + w[j] - 1) : (b * PP);  // dummy safe addr
        pt[j] = reinterpret_cast<const float4*>(pcloud)[src];
    }

    float4 dq, ilq;
    float* dv  = &dq.x;
    float* ilv = &ilq.x;
    #pragma unroll
    for (int j = 0; j < 4; j++) {
        float d = 0.0f, il = 0.0f;
        if (w[j] > 0) {
            float px = M[0]*pt[j].x + M[1]*pt[j].y + M[2] *pt[j].z + M[3];
            float py = M[4]*pt[j].x + M[5]*pt[j].y + M[6] *pt[j].z + M[7];
            float z  = M[8]*pt[j].x + M[9]*pt[j].y + M[10]*pt[j].z + M[11];

            float denom = fmaxf(z, 1e-6f);
            float x_ = px / denom;
            float y_ = py / denom;

            bool v = (x_ > -0.5f) & (x_ < (float)WW - 0.5f) &
                     (y_ > -0.5f) & (y_ < (float)HH - 0.5f) & (z > 0.0f);
            float valid = v ? 1.0f : 0.0f;
            float depth = fminf(fmaxf(z, 0.0f), (float)(BEV/2 - 1)) * valid;
            float vilu  = fminf(fmaxf(pt[j].w * valid, 0.0f), 255.0f);

            d  = depth * 0.01f;                           // depth / (bev/2)
            il = log1pf(vilu) * 0.18033688011112042f;     // log1p / ln(256)
        }
        dv[j]  = d;
        ilv[j] = il;
    }

    reinterpret_cast<float4*>(out)[(bn * 2    ) * (HW / 4) + q] = dq;
    reinterpret_cast<float4*>(out)[(bn * 2 + 1) * (HW / 4) + q] = ilq;
}

// ---------------- launch ----------------------------------------------------
extern "C" void kernel_launch(void* const* d_in, const int* in_sizes, int n_in,
                              void* d_out, int out_size)
{
    const float* pc = (const float*)d_in[0];  // pcloud
    const float* E  = (const float*)d_in[1];  // extrinsics
    const float* K  = (const float*)d_in[2];  // intrinsics
    const float* V  = (const float*)d_in[3];  // view
    float* out = (float*)d_out;

    k_setup<<<(BSN * HW / 4) / 256, 256>>>(E, K, V);   // 2100 blocks exact
    k_points<<<(BB * PP) / 256, 256>>>(pc);            // 4375 blocks exact
    dim3 cgrid((HW / 4 + 255) / 256, BSN);             // 22 x 96 blocks
    k_cells<<<cgrid, 256>>>(pc, out);
}